// round 7
// baseline (speedup 1.0000x reference)
#include <cuda_runtime.h>
#include <cstdint>

// DipolePredictorE3NN — R7: 4 consecutive batches per CTA (512 threads) to
// coarsen DRAM streams (256 CTAs x 2 long streams instead of 1024 x 2 short).
//   d_in[0] feats [B,N,7] f32 | d_in[1] coors [B,N,3] f32 | d_in[2] adj (UNUSED)
//   d_in[3] W_tp[7] | d_in[4] W1[128,3] | d_in[5] b1[128] | d_in[6] W2[3,128] | d_in[7] b2[3]
// Output: [B,3] f32

#define NS 7
#define HID 128
#define N_FIXED 512
#define BPC 4              // batches per CTA (fast path)
#define TPB (128 * BPC)    // 512 threads

// ---------------- fast path: N==512, B % 4 == 0 ----------------
__global__ __launch_bounds__(TPB, 2)
void dipole_wide_kernel(const float* __restrict__ feats,
                        const float* __restrict__ coors,
                        const float* __restrict__ W_tp,
                        const float* __restrict__ W1,
                        const float* __restrict__ b1,
                        const float* __restrict__ W2,
                        const float* __restrict__ b2,
                        float* __restrict__ out)
{
    const int tid  = threadIdx.x;
    const int lane = tid & 31;
    const int wid  = tid >> 5;              // 0..15
    const int bl   = tid >> 7;              // batch-local 0..3
    const int g    = tid & 127;             // node-group 0..127 (4 nodes each)
    const int b0   = blockIdx.x * BPC;
    const int b    = b0 + bl;

    float w[NS];
#pragma unroll
    for (int i = 0; i < NS; i++) w[i] = __ldg(&W_tp[i]);

    // Per-thread loads: 7x LDG.128 feats + 3x LDG.128 coors, all front-batched.
    const float4* f4 = reinterpret_cast<const float4*>(
        feats + (size_t)b * N_FIXED * NS) + g * 7;
    const float4* c4 = reinterpret_cast<const float4*>(
        coors + (size_t)b * N_FIXED * 3) + g * 3;

    float4 ff4[7];
#pragma unroll
    for (int i = 0; i < 7; i++) ff4[i] = __ldg(&f4[i]);
    float4 cc4[3];
#pragma unroll
    for (int i = 0; i < 3; i++) cc4[i] = __ldg(&c4[i]);

    const float* ff = reinterpret_cast<const float*>(ff4);
    const float* cc = reinterpret_cast<const float*>(cc4);

    float ax = 0.f, ay = 0.f, az = 0.f;
#pragma unroll
    for (int j = 0; j < 4; j++) {
        float s = 0.f;
#pragma unroll
        for (int i = 0; i < NS; i++) s = fmaf(ff[j * NS + i], w[i], s);
        ax = fmaf(s, cc[j * 3 + 0], ax);
        ay = fmaf(s, cc[j * 3 + 1], ay);
        az = fmaf(s, cc[j * 3 + 2], az);
    }

    // Warp reduce (each warp belongs entirely to one batch: 4 warps per batch).
#pragma unroll
    for (int o = 16; o > 0; o >>= 1) {
        ax += __shfl_down_sync(0xFFFFFFFFu, ax, o);
        ay += __shfl_down_sync(0xFFFFFFFFu, ay, o);
        az += __shfl_down_sync(0xFFFFFFFFu, az, o);
    }

    // Partials: sp[batch_local][warp_in_batch][xyz]
    __shared__ float sp[BPC][4][3];
    if (lane == 0) {
        sp[wid >> 2][wid & 3][0] = ax;
        sp[wid >> 2][wid & 3][1] = ay;
        sp[wid >> 2][wid & 3][2] = az;
    }
    __syncthreads();

    // Warps 0..3 each finish one batch (reduce 4 partials + MLP) in parallel.
    if (wid < BPC) {
        const int bb = b0 + wid;
        float px = (lane < 4) ? sp[wid][lane][0] : 0.f;
        float py = (lane < 4) ? sp[wid][lane][1] : 0.f;
        float pz = (lane < 4) ? sp[wid][lane][2] : 0.f;
#pragma unroll
        for (int o = 2; o > 0; o >>= 1) {
            px += __shfl_down_sync(0xFFFFFFFFu, px, o);
            py += __shfl_down_sync(0xFFFFFFFFu, py, o);
            pz += __shfl_down_sync(0xFFFFFFFFu, pz, o);
        }
        const float scale = 0.3779644730092272f / (float)N_FIXED;  // 1/sqrt(7)/N
        float g0 = __shfl_sync(0xFFFFFFFFu, px, 0) * scale;
        float g1 = __shfl_sync(0xFFFFFFFFu, py, 0) * scale;
        float g2 = __shfl_sync(0xFFFFFFFFu, pz, 0) * scale;

        float o0 = 0.f, o1 = 0.f, o2 = 0.f;
#pragma unroll
        for (int r = 0; r < HID / 32; r++) {
            int j = lane + r * 32;
            float h = fmaf(W1[j * 3 + 0], g0,
                      fmaf(W1[j * 3 + 1], g1,
                      fmaf(W1[j * 3 + 2], g2, b1[j])));
            h = fmaxf(h, 0.f);
            o0 = fmaf(W2[0 * HID + j], h, o0);
            o1 = fmaf(W2[1 * HID + j], h, o1);
            o2 = fmaf(W2[2 * HID + j], h, o2);
        }
#pragma unroll
        for (int o = 16; o > 0; o >>= 1) {
            o0 += __shfl_down_sync(0xFFFFFFFFu, o0, o);
            o1 += __shfl_down_sync(0xFFFFFFFFu, o1, o);
            o2 += __shfl_down_sync(0xFFFFFFFFu, o2, o);
        }
        if (lane == 0) {
            out[bb * 3 + 0] = o0 + b2[0];
            out[bb * 3 + 1] = o1 + b2[1];
            out[bb * 3 + 2] = o2 + b2[2];
        }
    }
}

// ---------------- generic fallback (any N, any B) ----------------
#define FTHREADS 128
__global__ __launch_bounds__(FTHREADS)
void dipole_ldg_kernel(const float* __restrict__ feats,
                       const float* __restrict__ coors,
                       const float* __restrict__ W_tp,
                       const float* __restrict__ W1,
                       const float* __restrict__ b1,
                       const float* __restrict__ W2,
                       const float* __restrict__ b2,
                       float* __restrict__ out,
                       int N)
{
    const int b    = blockIdx.x;
    const int tid  = threadIdx.x;
    const int lane = tid & 31;
    const int wid  = tid >> 5;
    float w[NS];
#pragma unroll
    for (int i = 0; i < NS; i++) w[i] = __ldg(&W_tp[i]);
    const float* fb = feats + (size_t)b * N * NS;
    const float* cb = coors + (size_t)b * N * 3;
    float ax = 0.f, ay = 0.f, az = 0.f;
    for (int n = tid; n < N; n += FTHREADS) {
        const float* fr = fb + (size_t)n * NS;
        float s = 0.f;
#pragma unroll
        for (int i = 0; i < NS; i++) s = fmaf(fr[i], w[i], s);
        const float* cr = cb + (size_t)n * 3;
        ax = fmaf(s, cr[0], ax);
        ay = fmaf(s, cr[1], ay);
        az = fmaf(s, cr[2], az);
    }
#pragma unroll
    for (int o = 16; o > 0; o >>= 1) {
        ax += __shfl_down_sync(0xFFFFFFFFu, ax, o);
        ay += __shfl_down_sync(0xFFFFFFFFu, ay, o);
        az += __shfl_down_sync(0xFFFFFFFFu, az, o);
    }
    __shared__ float sx[4], sy[4], sz[4];
    if (lane == 0) { sx[wid] = ax; sy[wid] = ay; sz[wid] = az; }
    __syncthreads();
    if (wid == 0) {
        float rx = (lane < 4) ? sx[lane] : 0.f;
        float ry = (lane < 4) ? sy[lane] : 0.f;
        float rz = (lane < 4) ? sz[lane] : 0.f;
#pragma unroll
        for (int o = 2; o > 0; o >>= 1) {
            rx += __shfl_down_sync(0xFFFFFFFFu, rx, o);
            ry += __shfl_down_sync(0xFFFFFFFFu, ry, o);
            rz += __shfl_down_sync(0xFFFFFFFFu, rz, o);
        }
        const float scale = 0.3779644730092272f / (float)N;
        float g0 = __shfl_sync(0xFFFFFFFFu, rx, 0) * scale;
        float g1 = __shfl_sync(0xFFFFFFFFu, ry, 0) * scale;
        float g2 = __shfl_sync(0xFFFFFFFFu, rz, 0) * scale;
        float o0 = 0.f, o1 = 0.f, o2 = 0.f;
#pragma unroll
        for (int r = 0; r < HID / 32; r++) {
            int j = lane + r * 32;
            float h = fmaf(W1[j * 3 + 0], g0,
                      fmaf(W1[j * 3 + 1], g1,
                      fmaf(W1[j * 3 + 2], g2, b1[j])));
            h = fmaxf(h, 0.f);
            o0 = fmaf(W2[0 * HID + j], h, o0);
            o1 = fmaf(W2[1 * HID + j], h, o1);
            o2 = fmaf(W2[2 * HID + j], h, o2);
        }
#pragma unroll
        for (int o = 16; o > 0; o >>= 1) {
            o0 += __shfl_down_sync(0xFFFFFFFFu, o0, o);
            o1 += __shfl_down_sync(0xFFFFFFFFu, o1, o);
            o2 += __shfl_down_sync(0xFFFFFFFFu, o2, o);
        }
        if (lane == 0) {
            out[b * 3 + 0] = o0 + b2[0];
            out[b * 3 + 1] = o1 + b2[1];
            out[b * 3 + 2] = o2 + b2[2];
        }
    }
}

extern "C" void kernel_launch(void* const* d_in, const int* in_sizes, int n_in,
                              void* d_out, int out_size)
{
    const float* feats = (const float*)d_in[0];
    const float* coors = (const float*)d_in[1];
    // d_in[2] = adj_mat, intentionally unused
    const float* W_tp  = (const float*)d_in[3];
    const float* W1    = (const float*)d_in[4];
    const float* b1    = (const float*)d_in[5];
    const float* W2    = (const float*)d_in[6];
    const float* b2    = (const float*)d_in[7];
    float* out = (float*)d_out;

    const int B = out_size / 3;           // output [B,3]
    const int N = in_sizes[1] / (B * 3);  // coors [B,N,3]

    if (N == N_FIXED && (B % BPC) == 0) {
        dipole_wide_kernel<<<B / BPC, TPB>>>(feats, coors, W_tp, W1, b1, W2, b2, out);
    } else {
        dipole_ldg_kernel<<<B, FTHREADS>>>(feats, coors, W_tp, W1, b1, W2, b2, out, N);
    }
}

// round 8
// speedup vs baseline: 1.0072x; 1.0072x over previous
#include <cuda_runtime.h>
#include <cstdint>

// DipolePredictorE3NN — R8: 256-bit loads (LDG.E.256), 8 nodes/thread.
// Halves chip-wide request count at constant bytes to test per-request-rate wall.
//   d_in[0] feats [B,N,7] f32 | d_in[1] coors [B,N,3] f32 | d_in[2] adj (UNUSED)
//   d_in[3] W_tp[7] | d_in[4] W1[128,3] | d_in[5] b1[128] | d_in[6] W2[3,128] | d_in[7] b2[3]
// Output: [B,3] f32

#define NS 7
#define HID 128
#define N_FIXED 512
#define BPC 4                   // batches per CTA
#define TPB (64 * BPC)          // 64 threads per batch (8 nodes each) = 256

// 256-bit read-only global load (sm_100a+): 8 f32 per instruction.
#define LDG256(d, p)                                                          \
    asm volatile("ld.global.nc.v8.f32 {%0,%1,%2,%3,%4,%5,%6,%7}, [%8];"       \
        : "=f"((d)[0]), "=f"((d)[1]), "=f"((d)[2]), "=f"((d)[3]),             \
          "=f"((d)[4]), "=f"((d)[5]), "=f"((d)[6]), "=f"((d)[7])              \
        : "l"(p))

// ---------------- fast path: N==512, B % 4 == 0 ----------------
__global__ __launch_bounds__(TPB, 4)
void dipole_v8_kernel(const float* __restrict__ feats,
                      const float* __restrict__ coors,
                      const float* __restrict__ W_tp,
                      const float* __restrict__ W1,
                      const float* __restrict__ b1,
                      const float* __restrict__ W2,
                      const float* __restrict__ b2,
                      float* __restrict__ out)
{
    const int tid  = threadIdx.x;
    const int lane = tid & 31;
    const int wid  = tid >> 5;           // 0..7
    const int bl   = tid >> 6;           // batch-local 0..3
    const int u    = tid & 63;           // thread-in-batch: owns nodes [u*8, u*8+8)
    const int b0   = blockIdx.x * BPC;
    const int b    = b0 + bl;

    float w[NS];
#pragma unroll
    for (int i = 0; i < NS; i++) w[i] = __ldg(&W_tp[i]);

    // feats slice: 8 nodes * 7 = 56 floats = 7 x v8 (base u*224 B, 32B-aligned)
    // coors slice: 8 nodes * 3 = 24 floats = 3 x v8 (base u*96 B, 32B-aligned)
    const float* fp = feats + (size_t)b * N_FIXED * NS + (size_t)u * 56;
    const float* cp = coors + (size_t)b * N_FIXED * 3 + (size_t)u * 24;

    float ff[56];
#pragma unroll
    for (int i = 0; i < 7; i++) LDG256(ff + i * 8, fp + i * 8);
    float cc[24];
#pragma unroll
    for (int i = 0; i < 3; i++) LDG256(cc + i * 8, cp + i * 8);

    float ax = 0.f, ay = 0.f, az = 0.f;
#pragma unroll
    for (int j = 0; j < 8; j++) {
        float s = 0.f;
#pragma unroll
        for (int i = 0; i < NS; i++) s = fmaf(ff[j * NS + i], w[i], s);
        ax = fmaf(s, cc[j * 3 + 0], ax);
        ay = fmaf(s, cc[j * 3 + 1], ay);
        az = fmaf(s, cc[j * 3 + 2], az);
    }

    // Warp reduce (each warp entirely within one batch: 2 warps per batch).
#pragma unroll
    for (int o = 16; o > 0; o >>= 1) {
        ax += __shfl_down_sync(0xFFFFFFFFu, ax, o);
        ay += __shfl_down_sync(0xFFFFFFFFu, ay, o);
        az += __shfl_down_sync(0xFFFFFFFFu, az, o);
    }

    __shared__ float sp[BPC][2][3];   // [batch_local][warp_in_batch][xyz]
    if (lane == 0) {
        sp[wid >> 1][wid & 1][0] = ax;
        sp[wid >> 1][wid & 1][1] = ay;
        sp[wid >> 1][wid & 1][2] = az;
    }
    __syncthreads();

    // Warps 0..3 each finish one batch (combine 2 partials + MLP) in parallel.
    if (wid < BPC) {
        const int bb = b0 + wid;
        const float scale = 0.3779644730092272f / (float)N_FIXED;  // 1/sqrt(7)/N
        float g0 = (sp[wid][0][0] + sp[wid][1][0]) * scale;
        float g1 = (sp[wid][0][1] + sp[wid][1][1]) * scale;
        float g2 = (sp[wid][0][2] + sp[wid][1][2]) * scale;

        float o0 = 0.f, o1 = 0.f, o2 = 0.f;
#pragma unroll
        for (int r = 0; r < HID / 32; r++) {
            int j = lane + r * 32;
            float h = fmaf(W1[j * 3 + 0], g0,
                      fmaf(W1[j * 3 + 1], g1,
                      fmaf(W1[j * 3 + 2], g2, b1[j])));
            h = fmaxf(h, 0.f);
            o0 = fmaf(W2[0 * HID + j], h, o0);
            o1 = fmaf(W2[1 * HID + j], h, o1);
            o2 = fmaf(W2[2 * HID + j], h, o2);
        }
#pragma unroll
        for (int o = 16; o > 0; o >>= 1) {
            o0 += __shfl_down_sync(0xFFFFFFFFu, o0, o);
            o1 += __shfl_down_sync(0xFFFFFFFFu, o1, o);
            o2 += __shfl_down_sync(0xFFFFFFFFu, o2, o);
        }
        if (lane == 0) {
            out[bb * 3 + 0] = o0 + b2[0];
            out[bb * 3 + 1] = o1 + b2[1];
            out[bb * 3 + 2] = o2 + b2[2];
        }
    }
}

// ---------------- generic fallback (any N, any B) ----------------
#define FTHREADS 128
__global__ __launch_bounds__(FTHREADS)
void dipole_ldg_kernel(const float* __restrict__ feats,
                       const float* __restrict__ coors,
                       const float* __restrict__ W_tp,
                       const float* __restrict__ W1,
                       const float* __restrict__ b1,
                       const float* __restrict__ W2,
                       const float* __restrict__ b2,
                       float* __restrict__ out,
                       int N)
{
    const int b    = blockIdx.x;
    const int tid  = threadIdx.x;
    const int lane = tid & 31;
    const int wid  = tid >> 5;
    float w[NS];
#pragma unroll
    for (int i = 0; i < NS; i++) w[i] = __ldg(&W_tp[i]);
    const float* fb = feats + (size_t)b * N * NS;
    const float* cb = coors + (size_t)b * N * 3;
    float ax = 0.f, ay = 0.f, az = 0.f;
    for (int n = tid; n < N; n += FTHREADS) {
        const float* fr = fb + (size_t)n * NS;
        float s = 0.f;
#pragma unroll
        for (int i = 0; i < NS; i++) s = fmaf(fr[i], w[i], s);
        const float* cr = cb + (size_t)n * 3;
        ax = fmaf(s, cr[0], ax);
        ay = fmaf(s, cr[1], ay);
        az = fmaf(s, cr[2], az);
    }
#pragma unroll
    for (int o = 16; o > 0; o >>= 1) {
        ax += __shfl_down_sync(0xFFFFFFFFu, ax, o);
        ay += __shfl_down_sync(0xFFFFFFFFu, ay, o);
        az += __shfl_down_sync(0xFFFFFFFFu, az, o);
    }
    __shared__ float sx[4], sy[4], sz[4];
    if (lane == 0) { sx[wid] = ax; sy[wid] = ay; sz[wid] = az; }
    __syncthreads();
    if (wid == 0) {
        float rx = (lane < 4) ? sx[lane] : 0.f;
        float ry = (lane < 4) ? sy[lane] : 0.f;
        float rz = (lane < 4) ? sz[lane] : 0.f;
#pragma unroll
        for (int o = 2; o > 0; o >>= 1) {
            rx += __shfl_down_sync(0xFFFFFFFFu, rx, o);
            ry += __shfl_down_sync(0xFFFFFFFFu, ry, o);
            rz += __shfl_down_sync(0xFFFFFFFFu, rz, o);
        }
        const float scale = 0.3779644730092272f / (float)N;
        float g0 = __shfl_sync(0xFFFFFFFFu, rx, 0) * scale;
        float g1 = __shfl_sync(0xFFFFFFFFu, ry, 0) * scale;
        float g2 = __shfl_sync(0xFFFFFFFFu, rz, 0) * scale;
        float o0 = 0.f, o1 = 0.f, o2 = 0.f;
#pragma unroll
        for (int r = 0; r < HID / 32; r++) {
            int j = lane + r * 32;
            float h = fmaf(W1[j * 3 + 0], g0,
                      fmaf(W1[j * 3 + 1], g1,
                      fmaf(W1[j * 3 + 2], g2, b1[j])));
            h = fmaxf(h, 0.f);
            o0 = fmaf(W2[0 * HID + j], h, o0);
            o1 = fmaf(W2[1 * HID + j], h, o1);
            o2 = fmaf(W2[2 * HID + j], h, o2);
        }
#pragma unroll
        for (int o = 16; o > 0; o >>= 1) {
            o0 += __shfl_down_sync(0xFFFFFFFFu, o0, o);
            o1 += __shfl_down_sync(0xFFFFFFFFu, o1, o);
            o2 += __shfl_down_sync(0xFFFFFFFFu, o2, o);
        }
        if (lane == 0) {
            out[b * 3 + 0] = o0 + b2[0];
            out[b * 3 + 1] = o1 + b2[1];
            out[b * 3 + 2] = o2 + b2[2];
        }
    }
}

extern "C" void kernel_launch(void* const* d_in, const int* in_sizes, int n_in,
                              void* d_out, int out_size)
{
    const float* feats = (const float*)d_in[0];
    const float* coors = (const float*)d_in[1];
    // d_in[2] = adj_mat, intentionally unused
    const float* W_tp  = (const float*)d_in[3];
    const float* W1    = (const float*)d_in[4];
    const float* b1    = (const float*)d_in[5];
    const float* W2    = (const float*)d_in[6];
    const float* b2    = (const float*)d_in[7];
    float* out = (float*)d_out;

    const int B = out_size / 3;           // output [B,3]
    const int N = in_sizes[1] / (B * 3);  // coors [B,N,3]

    if (N == N_FIXED && (B % BPC) == 0) {
        dipole_v8_kernel<<<B / BPC, TPB>>>(feats, coors, W_tp, W1, b1, W2, b2, out);
    } else {
        dipole_ldg_kernel<<<B, FTHREADS>>>(feats, coors, W_tp, W1, b1, W2, b2, out, N);
    }
}

// round 10
// speedup vs baseline: 1.0295x; 1.0221x over previous
#include <cuda_runtime.h>
#include <cstdint>

// DipolePredictorE3NN — R10: L2-persistence via 256-bit evict_last loads.
// (ptxas requires .v8.f32 width for .L2::evict_last on sm_100a.)
// Working set (21MB) fits L2 (~126MB); graph replays re-read the same buffers,
// so retaining lines in L2 should lift warm-replay bandwidth past the 2.6TB/s
// DRAM-path wall observed in R3-R8.
//   d_in[0] feats [B,N,7] f32 | d_in[1] coors [B,N,3] f32 | d_in[2] adj (UNUSED)
//   d_in[3] W_tp[7] | d_in[4] W1[128,3] | d_in[5] b1[128] | d_in[6] W2[3,128] | d_in[7] b2[3]
// Output: [B,3] f32

#define NS 7
#define HID 128
#define N_FIXED 512
#define BPC 4                   // batches per CTA
#define TPB (64 * BPC)          // 64 threads per batch (8 nodes each) = 256

// 256-bit global load with L2 evict-last residency hint.
#define LDG256_EL(d, p)                                                       \
    asm volatile(                                                             \
        "ld.global.L2::evict_last.v8.f32 {%0,%1,%2,%3,%4,%5,%6,%7}, [%8];"    \
        : "=f"((d)[0]), "=f"((d)[1]), "=f"((d)[2]), "=f"((d)[3]),             \
          "=f"((d)[4]), "=f"((d)[5]), "=f"((d)[6]), "=f"((d)[7])              \
        : "l"(p))

// ---------------- fast path: N==512, B % 4 == 0 ----------------
__global__ __launch_bounds__(TPB, 4)
void dipole_v8el_kernel(const float* __restrict__ feats,
                        const float* __restrict__ coors,
                        const float* __restrict__ W_tp,
                        const float* __restrict__ W1,
                        const float* __restrict__ b1,
                        const float* __restrict__ W2,
                        const float* __restrict__ b2,
                        float* __restrict__ out)
{
    const int tid  = threadIdx.x;
    const int lane = tid & 31;
    const int wid  = tid >> 5;           // 0..7
    const int bl   = tid >> 6;           // batch-local 0..3
    const int u    = tid & 63;           // thread-in-batch: nodes [u*8, u*8+8)
    const int b0   = blockIdx.x * BPC;
    const int b    = b0 + bl;

    float w[NS];
#pragma unroll
    for (int i = 0; i < NS; i++) w[i] = __ldg(&W_tp[i]);

    // feats slice: 8 nodes * 7 = 56 floats = 7 x v8 (base u*224 B, 32B-aligned)
    // coors slice: 8 nodes * 3 = 24 floats = 3 x v8 (base u*96 B, 32B-aligned)
    const float* fp = feats + (size_t)b * N_FIXED * NS + (size_t)u * 56;
    const float* cp = coors + (size_t)b * N_FIXED * 3 + (size_t)u * 24;

    float ff[56];
#pragma unroll
    for (int i = 0; i < 7; i++) LDG256_EL(ff + i * 8, fp + i * 8);
    float cc[24];
#pragma unroll
    for (int i = 0; i < 3; i++) LDG256_EL(cc + i * 8, cp + i * 8);

    float ax = 0.f, ay = 0.f, az = 0.f;
#pragma unroll
    for (int j = 0; j < 8; j++) {
        float s = 0.f;
#pragma unroll
        for (int i = 0; i < NS; i++) s = fmaf(ff[j * NS + i], w[i], s);
        ax = fmaf(s, cc[j * 3 + 0], ax);
        ay = fmaf(s, cc[j * 3 + 1], ay);
        az = fmaf(s, cc[j * 3 + 2], az);
    }

    // Warp reduce (each warp entirely within one batch: 2 warps per batch).
#pragma unroll
    for (int o = 16; o > 0; o >>= 1) {
        ax += __shfl_down_sync(0xFFFFFFFFu, ax, o);
        ay += __shfl_down_sync(0xFFFFFFFFu, ay, o);
        az += __shfl_down_sync(0xFFFFFFFFu, az, o);
    }

    __shared__ float sp[BPC][2][3];   // [batch_local][warp_in_batch][xyz]
    if (lane == 0) {
        sp[wid >> 1][wid & 1][0] = ax;
        sp[wid >> 1][wid & 1][1] = ay;
        sp[wid >> 1][wid & 1][2] = az;
    }
    __syncthreads();

    // Warps 0..3 each finish one batch (combine 2 partials + MLP) in parallel.
    if (wid < BPC) {
        const int bb = b0 + wid;
        const float scale = 0.3779644730092272f / (float)N_FIXED;  // 1/sqrt(7)/N
        float g0 = (sp[wid][0][0] + sp[wid][1][0]) * scale;
        float g1 = (sp[wid][0][1] + sp[wid][1][1]) * scale;
        float g2 = (sp[wid][0][2] + sp[wid][1][2]) * scale;

        float o0 = 0.f, o1 = 0.f, o2 = 0.f;
#pragma unroll
        for (int r = 0; r < HID / 32; r++) {
            int j = lane + r * 32;
            float h = fmaf(W1[j * 3 + 0], g0,
                      fmaf(W1[j * 3 + 1], g1,
                      fmaf(W1[j * 3 + 2], g2, b1[j])));
            h = fmaxf(h, 0.f);
            o0 = fmaf(W2[0 * HID + j], h, o0);
            o1 = fmaf(W2[1 * HID + j], h, o1);
            o2 = fmaf(W2[2 * HID + j], h, o2);
        }
#pragma unroll
        for (int o = 16; o > 0; o >>= 1) {
            o0 += __shfl_down_sync(0xFFFFFFFFu, o0, o);
            o1 += __shfl_down_sync(0xFFFFFFFFu, o1, o);
            o2 += __shfl_down_sync(0xFFFFFFFFu, o2, o);
        }
        if (lane == 0) {
            out[bb * 3 + 0] = o0 + b2[0];
            out[bb * 3 + 1] = o1 + b2[1];
            out[bb * 3 + 2] = o2 + b2[2];
        }
    }
}

// ---------------- generic fallback (any N, any B) ----------------
#define FTHREADS 128
__global__ __launch_bounds__(FTHREADS)
void dipole_ldg_kernel(const float* __restrict__ feats,
                       const float* __restrict__ coors,
                       const float* __restrict__ W_tp,
                       const float* __restrict__ W1,
                       const float* __restrict__ b1,
                       const float* __restrict__ W2,
                       const float* __restrict__ b2,
                       float* __restrict__ out,
                       int N)
{
    const int b    = blockIdx.x;
    const int tid  = threadIdx.x;
    const int lane = tid & 31;
    const int wid  = tid >> 5;
    float w[NS];
#pragma unroll
    for (int i = 0; i < NS; i++) w[i] = __ldg(&W_tp[i]);
    const float* fb = feats + (size_t)b * N * NS;
    const float* cb = coors + (size_t)b * N * 3;
    float ax = 0.f, ay = 0.f, az = 0.f;
    for (int n = tid; n < N; n += FTHREADS) {
        const float* fr = fb + (size_t)n * NS;
        float s = 0.f;
#pragma unroll
        for (int i = 0; i < NS; i++) s = fmaf(fr[i], w[i], s);
        const float* cr = cb + (size_t)n * 3;
        ax = fmaf(s, cr[0], ax);
        ay = fmaf(s, cr[1], ay);
        az = fmaf(s, cr[2], az);
    }
#pragma unroll
    for (int o = 16; o > 0; o >>= 1) {
        ax += __shfl_down_sync(0xFFFFFFFFu, ax, o);
        ay += __shfl_down_sync(0xFFFFFFFFu, ay, o);
        az += __shfl_down_sync(0xFFFFFFFFu, az, o);
    }
    __shared__ float sx[4], sy[4], sz[4];
    if (lane == 0) { sx[wid] = ax; sy[wid] = ay; sz[wid] = az; }
    __syncthreads();
    if (wid == 0) {
        float rx = (lane < 4) ? sx[lane] : 0.f;
        float ry = (lane < 4) ? sy[lane] : 0.f;
        float rz = (lane < 4) ? sz[lane] : 0.f;
#pragma unroll
        for (int o = 2; o > 0; o >>= 1) {
            rx += __shfl_down_sync(0xFFFFFFFFu, rx, o);
            ry += __shfl_down_sync(0xFFFFFFFFu, ry, o);
            rz += __shfl_down_sync(0xFFFFFFFFu, rz, o);
        }
        const float scale = 0.3779644730092272f / (float)N;
        float g0 = __shfl_sync(0xFFFFFFFFu, rx, 0) * scale;
        float g1 = __shfl_sync(0xFFFFFFFFu, ry, 0) * scale;
        float g2 = __shfl_sync(0xFFFFFFFFu, rz, 0) * scale;
        float o0 = 0.f, o1 = 0.f, o2 = 0.f;
#pragma unroll
        for (int r = 0; r < HID / 32; r++) {
            int j = lane + r * 32;
            float h = fmaf(W1[j * 3 + 0], g0,
                      fmaf(W1[j * 3 + 1], g1,
                      fmaf(W1[j * 3 + 2], g2, b1[j])));
            h = fmaxf(h, 0.f);
            o0 = fmaf(W2[0 * HID + j], h, o0);
            o1 = fmaf(W2[1 * HID + j], h, o1);
            o2 = fmaf(W2[2 * HID + j], h, o2);
        }
#pragma unroll
        for (int o = 16; o > 0; o >>= 1) {
            o0 += __shfl_down_sync(0xFFFFFFFFu, o0, o);
            o1 += __shfl_down_sync(0xFFFFFFFFu, o1, o);
            o2 += __shfl_down_sync(0xFFFFFFFFu, o2, o);
        }
        if (lane == 0) {
            out[b * 3 + 0] = o0 + b2[0];
            out[b * 3 + 1] = o1 + b2[1];
            out[b * 3 + 2] = o2 + b2[2];
        }
    }
}

extern "C" void kernel_launch(void* const* d_in, const int* in_sizes, int n_in,
                              void* d_out, int out_size)
{
    const float* feats = (const float*)d_in[0];
    const float* coors = (const float*)d_in[1];
    // d_in[2] = adj_mat, intentionally unused
    const float* W_tp  = (const float*)d_in[3];
    const float* W1    = (const float*)d_in[4];
    const float* b1    = (const float*)d_in[5];
    const float* W2    = (const float*)d_in[6];
    const float* b2    = (const float*)d_in[7];
    float* out = (float*)d_out;

    const int B = out_size / 3;           // output [B,3]
    const int N = in_sizes[1] / (B * 3);  // coors [B,N,3]

    if (N == N_FIXED && (B % BPC) == 0) {
        dipole_v8el_kernel<<<B / BPC, TPB>>>(feats, coors, W_tp, W1, b1, W2, b2, out);
    } else {
        dipole_ldg_kernel<<<B, FTHREADS>>>(feats, coors, W_tp, W1, b1, W2, b2, out, N);
    }
}

// round 11
// speedup vs baseline: 1.0690x; 1.0383x over previous
#include <cuda_runtime.h>
#include <cstdint>

// DipolePredictorE3NN — R11: accept ~2.7TB/s environmental BW ceiling; minimize
// residue around it. grid=B (1024) small CTAs for CLC balance, v8 (256-bit)
// loads issued first, shortest possible post-load tail.
//   d_in[0] feats [B,N,7] f32 | d_in[1] coors [B,N,3] f32 | d_in[2] adj (UNUSED)
//   d_in[3] W_tp[7] | d_in[4] W1[128,3] | d_in[5] b1[128] | d_in[6] W2[3,128] | d_in[7] b2[3]
// Output: [B,3] f32

#define NS 7
#define HID 128
#define N_FIXED 512
#define TPB 64              // 64 threads: 8 nodes each -> covers N=512

// 256-bit read-only global load (sm_100a+).
#define LDG256(d, p)                                                          \
    asm volatile("ld.global.nc.v8.f32 {%0,%1,%2,%3,%4,%5,%6,%7}, [%8];"       \
        : "=f"((d)[0]), "=f"((d)[1]), "=f"((d)[2]), "=f"((d)[3]),             \
          "=f"((d)[4]), "=f"((d)[5]), "=f"((d)[6]), "=f"((d)[7])              \
        : "l"(p))

// ---------------- fast path: N==512 ----------------
__global__ __launch_bounds__(TPB)
void dipole_r11_kernel(const float* __restrict__ feats,
                       const float* __restrict__ coors,
                       const float* __restrict__ W_tp,
                       const float* __restrict__ W1,
                       const float* __restrict__ b1,
                       const float* __restrict__ W2,
                       const float* __restrict__ b2,
                       float* __restrict__ out)
{
    const int b    = blockIdx.x;
    const int tid  = threadIdx.x;          // 0..63, owns nodes [tid*8, tid*8+8)
    const int lane = tid & 31;
    const int wid  = tid >> 5;             // 0 or 1

    // Issue the big tile loads FIRST so DRAM round-trip starts immediately.
    // feats slice: 56 floats = 7 x v8 (base tid*224B, 32B-aligned)
    // coors slice: 24 floats = 3 x v8 (base tid*96B, 32B-aligned)
    const float* fp = feats + (size_t)b * N_FIXED * NS + (size_t)tid * 56;
    const float* cp = coors + (size_t)b * N_FIXED * 3 + (size_t)tid * 24;

    float ff[56];
#pragma unroll
    for (int i = 0; i < 7; i++) LDG256(ff + i * 8, fp + i * 8);
    float cc[24];
#pragma unroll
    for (int i = 0; i < 3; i++) LDG256(cc + i * 8, cp + i * 8);

    // TP weights after (L2-resident broadcast; off the critical path).
    float w[NS];
#pragma unroll
    for (int i = 0; i < NS; i++) w[i] = __ldg(&W_tp[i]);

    float ax = 0.f, ay = 0.f, az = 0.f;
#pragma unroll
    for (int j = 0; j < 8; j++) {
        float s = 0.f;
#pragma unroll
        for (int i = 0; i < NS; i++) s = fmaf(ff[j * NS + i], w[i], s);
        ax = fmaf(s, cc[j * 3 + 0], ax);
        ay = fmaf(s, cc[j * 3 + 1], ay);
        az = fmaf(s, cc[j * 3 + 2], az);
    }

    // Warp reduce.
#pragma unroll
    for (int o = 16; o > 0; o >>= 1) {
        ax += __shfl_down_sync(0xFFFFFFFFu, ax, o);
        ay += __shfl_down_sync(0xFFFFFFFFu, ay, o);
        az += __shfl_down_sync(0xFFFFFFFFu, az, o);
    }

    // Warp 1 parks its partial; warp 0 finishes.
    __shared__ float sp[3];
    if (wid == 1 && lane == 0) { sp[0] = ax; sp[1] = ay; sp[2] = az; }
    __syncthreads();

    if (wid == 0) {
        const float scale = 0.3779644730092272f / (float)N_FIXED;  // 1/sqrt(7)/N
        float g0 = (__shfl_sync(0xFFFFFFFFu, ax, 0) + sp[0]) * scale;
        float g1 = (__shfl_sync(0xFFFFFFFFu, ay, 0) + sp[1]) * scale;
        float g2 = (__shfl_sync(0xFFFFFFFFu, az, 0) + sp[2]) * scale;

        // MLP: out = W2 @ relu(W1 @ g + b1) + b2 ; each lane owns 4 hidden units.
        float o0 = 0.f, o1 = 0.f, o2 = 0.f;
#pragma unroll
        for (int r = 0; r < HID / 32; r++) {
            int j = lane + r * 32;
            float h = fmaf(W1[j * 3 + 0], g0,
                      fmaf(W1[j * 3 + 1], g1,
                      fmaf(W1[j * 3 + 2], g2, b1[j])));
            h = fmaxf(h, 0.f);
            o0 = fmaf(W2[0 * HID + j], h, o0);
            o1 = fmaf(W2[1 * HID + j], h, o1);
            o2 = fmaf(W2[2 * HID + j], h, o2);
        }
#pragma unroll
        for (int o = 16; o > 0; o >>= 1) {
            o0 += __shfl_down_sync(0xFFFFFFFFu, o0, o);
            o1 += __shfl_down_sync(0xFFFFFFFFu, o1, o);
            o2 += __shfl_down_sync(0xFFFFFFFFu, o2, o);
        }
        if (lane == 0) {
            out[b * 3 + 0] = o0 + b2[0];
            out[b * 3 + 1] = o1 + b2[1];
            out[b * 3 + 2] = o2 + b2[2];
        }
    }
}

// ---------------- generic fallback (any N) ----------------
#define FTHREADS 128
__global__ __launch_bounds__(FTHREADS)
void dipole_ldg_kernel(const float* __restrict__ feats,
                       const float* __restrict__ coors,
                       const float* __restrict__ W_tp,
                       const float* __restrict__ W1,
                       const float* __restrict__ b1,
                       const float* __restrict__ W2,
                       const float* __restrict__ b2,
                       float* __restrict__ out,
                       int N)
{
    const int b    = blockIdx.x;
    const int tid  = threadIdx.x;
    const int lane = tid & 31;
    const int wid  = tid >> 5;
    float w[NS];
#pragma unroll
    for (int i = 0; i < NS; i++) w[i] = __ldg(&W_tp[i]);
    const float* fb = feats + (size_t)b * N * NS;
    const float* cb = coors + (size_t)b * N * 3;
    float ax = 0.f, ay = 0.f, az = 0.f;
    for (int n = tid; n < N; n += FTHREADS) {
        const float* fr = fb + (size_t)n * NS;
        float s = 0.f;
#pragma unroll
        for (int i = 0; i < NS; i++) s = fmaf(fr[i], w[i], s);
        const float* cr = cb + (size_t)n * 3;
        ax = fmaf(s, cr[0], ax);
        ay = fmaf(s, cr[1], ay);
        az = fmaf(s, cr[2], az);
    }
#pragma unroll
    for (int o = 16; o > 0; o >>= 1) {
        ax += __shfl_down_sync(0xFFFFFFFFu, ax, o);
        ay += __shfl_down_sync(0xFFFFFFFFu, ay, o);
        az += __shfl_down_sync(0xFFFFFFFFu, az, o);
    }
    __shared__ float sx[4], sy[4], sz[4];
    if (lane == 0) { sx[wid] = ax; sy[wid] = ay; sz[wid] = az; }
    __syncthreads();
    if (wid == 0) {
        float rx = (lane < 4) ? sx[lane] : 0.f;
        float ry = (lane < 4) ? sy[lane] : 0.f;
        float rz = (lane < 4) ? sz[lane] : 0.f;
#pragma unroll
        for (int o = 2; o > 0; o >>= 1) {
            rx += __shfl_down_sync(0xFFFFFFFFu, rx, o);
            ry += __shfl_down_sync(0xFFFFFFFFu, ry, o);
            rz += __shfl_down_sync(0xFFFFFFFFu, rz, o);
        }
        const float scale = 0.3779644730092272f / (float)N;
        float g0 = __shfl_sync(0xFFFFFFFFu, rx, 0) * scale;
        float g1 = __shfl_sync(0xFFFFFFFFu, ry, 0) * scale;
        float g2 = __shfl_sync(0xFFFFFFFFu, rz, 0) * scale;
        float o0 = 0.f, o1 = 0.f, o2 = 0.f;
#pragma unroll
        for (int r = 0; r < HID / 32; r++) {
            int j = lane + r * 32;
            float h = fmaf(W1[j * 3 + 0], g0,
                      fmaf(W1[j * 3 + 1], g1,
                      fmaf(W1[j * 3 + 2], g2, b1[j])));
            h = fmaxf(h, 0.f);
            o0 = fmaf(W2[0 * HID + j], h, o0);
            o1 = fmaf(W2[1 * HID + j], h, o1);
            o2 = fmaf(W2[2 * HID + j], h, o2);
        }
#pragma unroll
        for (int o = 16; o > 0; o >>= 1) {
            o0 += __shfl_down_sync(0xFFFFFFFFu, o0, o);
            o1 += __shfl_down_sync(0xFFFFFFFFu, o1, o);
            o2 += __shfl_down_sync(0xFFFFFFFFu, o2, o);
        }
        if (lane == 0) {
            out[b * 3 + 0] = o0 + b2[0];
            out[b * 3 + 1] = o1 + b2[1];
            out[b * 3 + 2] = o2 + b2[2];
        }
    }
}

extern "C" void kernel_launch(void* const* d_in, const int* in_sizes, int n_in,
                              void* d_out, int out_size)
{
    const float* feats = (const float*)d_in[0];
    const float* coors = (const float*)d_in[1];
    // d_in[2] = adj_mat, intentionally unused
    const float* W_tp  = (const float*)d_in[3];
    const float* W1    = (const float*)d_in[4];
    const float* b1    = (const float*)d_in[5];
    const float* W2    = (const float*)d_in[6];
    const float* b2    = (const float*)d_in[7];
    float* out = (float*)d_out;

    const int B = out_size / 3;           // output [B,3]
    const int N = in_sizes[1] / (B * 3);  // coors [B,N,3]

    if (N == N_FIXED) {
        dipole_r11_kernel<<<B, TPB>>>(feats, coors, W_tp, W1, b1, W2, b2, out);
    } else {
        dipole_ldg_kernel<<<B, FTHREADS>>>(feats, coors, W_tp, W1, b1, W2, b2, out, N);
    }
}

// round 12
// speedup vs baseline: 1.0941x; 1.0235x over previous
#include <cuda_runtime.h>
#include <cstdint>

// DipolePredictorE3NN — R12: R4 (best bench) + half-tile TMA pipelining.
// Established across R3-R11: ~2.6TB/s per-SM in-flight ceiling binds all
// transports equally; this round only shortens the end-of-CTA wait tail.
//   d_in[0] feats [B,N,7] f32 | d_in[1] coors [B,N,3] f32 | d_in[2] adj (UNUSED)
//   d_in[3] W_tp[7] | d_in[4] W1[128,3] | d_in[5] b1[128] | d_in[6] W2[3,128] | d_in[7] b2[3]
// Output: [B,3] f32

#define NS 7
#define HID 128
#define THREADS 128
#define N_FIXED 512
#define FEATS_BYTES (N_FIXED * NS * 4)   // 14336
#define HALF_FEATS  (FEATS_BYTES / 2)    // 7168 (= nodes 0..255 | 256..511)

__device__ __forceinline__ uint32_t smem_u32(const void* p) {
    uint32_t a;
    asm("{ .reg .u64 t; cvta.to.shared.u64 t, %1; cvt.u32.u64 %0, t; }"
        : "=r"(a) : "l"(p));
    return a;
}

__device__ __forceinline__ void mbar_wait0(uint32_t mbar) {
    uint32_t done;
    asm volatile(
        "{ .reg .pred p; mbarrier.try_wait.parity.shared.b64 p, [%1], 0; "
        "selp.b32 %0, 1, 0, p; }"
        : "=r"(done) : "r"(mbar) : "memory");
    if (!done) {
        asm volatile(
            "{ .reg .pred P1;\n"
            "W_%=: mbarrier.try_wait.parity.shared.b64 P1, [%0], 0, 0x989680;\n"
            "@P1 bra.uni D_%=;\n"
            "bra.uni W_%=;\n"
            "D_%=: }"
            :: "r"(mbar) : "memory");
    }
}

// ---------- fast path: N==512 ----------
__global__ __launch_bounds__(THREADS)
void dipole_r12_kernel(const float* __restrict__ feats,
                       const float* __restrict__ coors,
                       const float* __restrict__ W_tp,
                       const float* __restrict__ W1,
                       const float* __restrict__ b1,
                       const float* __restrict__ W2,
                       const float* __restrict__ b2,
                       float* __restrict__ out)
{
    __shared__ __align__(16) float s_feats[N_FIXED * NS];  // 14336 B
    __shared__ __align__(8)  uint64_t s_mbar[2];
    __shared__ float sx[4], sy[4], sz[4];

    const int b    = blockIdx.x;
    const int tid  = threadIdx.x;
    const int lane = tid & 31;
    const int wid  = tid >> 5;

    const uint32_t mb0 = smem_u32(&s_mbar[0]);
    const uint32_t mb1 = smem_u32(&s_mbar[1]);

    if (tid == 0) {
        asm volatile("mbarrier.init.shared.b64 [%0], 1;" :: "r"(mb0) : "memory");
        asm volatile("mbarrier.init.shared.b64 [%0], 1;" :: "r"(mb1) : "memory");
    }
    __syncthreads();

    if (tid == 0) {
        const char* gf = (const char*)(feats + (size_t)b * N_FIXED * NS);
        const uint32_t sf = smem_u32(s_feats);
        asm volatile("mbarrier.arrive.expect_tx.shared.b64 _, [%0], %1;"
                     :: "r"(mb0), "r"((uint32_t)HALF_FEATS) : "memory");
        asm volatile(
            "cp.async.bulk.shared::cta.global.mbarrier::complete_tx::bytes "
            "[%0], [%1], %2, [%3];"
            :: "r"(sf), "l"(gf), "r"((uint32_t)HALF_FEATS), "r"(mb0) : "memory");
        asm volatile("mbarrier.arrive.expect_tx.shared.b64 _, [%0], %1;"
                     :: "r"(mb1), "r"((uint32_t)HALF_FEATS) : "memory");
        asm volatile(
            "cp.async.bulk.shared::cta.global.mbarrier::complete_tx::bytes "
            "[%0], [%1], %2, [%3];"
            :: "r"(sf + HALF_FEATS), "l"(gf + HALF_FEATS),
               "r"((uint32_t)HALF_FEATS), "r"(mb1) : "memory");
    }

    // While TMA streams feats: coors (both halves) via LDG.128 into registers,
    // plus TP weights. Thread tid owns nodes {tid*2, tid*2+1} in each half:
    // half h, local pair p=tid -> nodes h*256 + p*2. coors pair = 24B; use
    // 3 scalar float2-ish loads: actually 2 nodes * 3 = 6 floats = 1.5 float4.
    // Simpler: half h nodes are covered by float4 groups of 4 nodes; thread
    // tid handles group (tid&63) of half (tid>>6)? Keep R4 mapping instead:
    // thread owns 4 consecutive nodes tid*4..tid*4+3 which live in half tid/64.
    float w[NS];
#pragma unroll
    for (int i = 0; i < NS; i++) w[i] = __ldg(&W_tp[i]);

    float4 cc4[3];
    {
        const float4* c4 = reinterpret_cast<const float4*>(
            coors + (size_t)b * N_FIXED * 3) + tid * 3;
#pragma unroll
        for (int i = 0; i < 3; i++) cc4[i] = __ldg(&c4[i]);
    }
    const float* cc = reinterpret_cast<const float*>(cc4);

    // Threads 0..63 own nodes in half 0; threads 64..127 own half 1.
    // Wait only for the half this thread needs; half 0 owners start sooner.
    if (tid < 64) mbar_wait0(mb0); else mbar_wait0(mb1);

    float ax = 0.f, ay = 0.f, az = 0.f;
    {
        const float4* f4 = reinterpret_cast<const float4*>(s_feats) + tid * 7;
        float4 ff4[7];
#pragma unroll
        for (int i = 0; i < 7; i++) ff4[i] = f4[i];
        const float* ff = reinterpret_cast<const float*>(ff4);
#pragma unroll
        for (int j = 0; j < 4; j++) {
            float s = 0.f;
#pragma unroll
            for (int i = 0; i < NS; i++) s = fmaf(ff[j * NS + i], w[i], s);
            ax = fmaf(s, cc[j * 3 + 0], ax);
            ay = fmaf(s, cc[j * 3 + 1], ay);
            az = fmaf(s, cc[j * 3 + 2], az);
        }
    }

#pragma unroll
    for (int o = 16; o > 0; o >>= 1) {
        ax += __shfl_down_sync(0xFFFFFFFFu, ax, o);
        ay += __shfl_down_sync(0xFFFFFFFFu, ay, o);
        az += __shfl_down_sync(0xFFFFFFFFu, az, o);
    }
    if (lane == 0) { sx[wid] = ax; sy[wid] = ay; sz[wid] = az; }
    __syncthreads();

    if (wid == 0) {
        float rx = (lane < 4) ? sx[lane] : 0.f;
        float ry = (lane < 4) ? sy[lane] : 0.f;
        float rz = (lane < 4) ? sz[lane] : 0.f;
#pragma unroll
        for (int o = 2; o > 0; o >>= 1) {
            rx += __shfl_down_sync(0xFFFFFFFFu, rx, o);
            ry += __shfl_down_sync(0xFFFFFFFFu, ry, o);
            rz += __shfl_down_sync(0xFFFFFFFFu, rz, o);
        }
        const float scale = 0.3779644730092272f / (float)N_FIXED;  // 1/sqrt(7)/N
        float g0 = __shfl_sync(0xFFFFFFFFu, rx, 0) * scale;
        float g1 = __shfl_sync(0xFFFFFFFFu, ry, 0) * scale;
        float g2 = __shfl_sync(0xFFFFFFFFu, rz, 0) * scale;

        float o0 = 0.f, o1 = 0.f, o2 = 0.f;
#pragma unroll
        for (int r = 0; r < HID / 32; r++) {
            int j = lane + r * 32;
            float h = fmaf(W1[j * 3 + 0], g0,
                      fmaf(W1[j * 3 + 1], g1,
                      fmaf(W1[j * 3 + 2], g2, b1[j])));
            h = fmaxf(h, 0.f);
            o0 = fmaf(W2[0 * HID + j], h, o0);
            o1 = fmaf(W2[1 * HID + j], h, o1);
            o2 = fmaf(W2[2 * HID + j], h, o2);
        }
#pragma unroll
        for (int o = 16; o > 0; o >>= 1) {
            o0 += __shfl_down_sync(0xFFFFFFFFu, o0, o);
            o1 += __shfl_down_sync(0xFFFFFFFFu, o1, o);
            o2 += __shfl_down_sync(0xFFFFFFFFu, o2, o);
        }
        if (lane == 0) {
            out[b * 3 + 0] = o0 + b2[0];
            out[b * 3 + 1] = o1 + b2[1];
            out[b * 3 + 2] = o2 + b2[2];
        }
    }
}

// ---------- generic fallback (any N) ----------
__global__ __launch_bounds__(THREADS)
void dipole_ldg_kernel(const float* __restrict__ feats,
                       const float* __restrict__ coors,
                       const float* __restrict__ W_tp,
                       const float* __restrict__ W1,
                       const float* __restrict__ b1,
                       const float* __restrict__ W2,
                       const float* __restrict__ b2,
                       float* __restrict__ out,
                       int N)
{
    const int b    = blockIdx.x;
    const int tid  = threadIdx.x;
    const int lane = tid & 31;
    const int wid  = tid >> 5;
    float w[NS];
#pragma unroll
    for (int i = 0; i < NS; i++) w[i] = __ldg(&W_tp[i]);
    const float* fb = feats + (size_t)b * N * NS;
    const float* cb = coors + (size_t)b * N * 3;
    float ax = 0.f, ay = 0.f, az = 0.f;
    for (int n = tid; n < N; n += THREADS) {
        const float* fr = fb + (size_t)n * NS;
        float s = 0.f;
#pragma unroll
        for (int i = 0; i < NS; i++) s = fmaf(fr[i], w[i], s);
        const float* cr = cb + (size_t)n * 3;
        ax = fmaf(s, cr[0], ax);
        ay = fmaf(s, cr[1], ay);
        az = fmaf(s, cr[2], az);
    }
#pragma unroll
    for (int o = 16; o > 0; o >>= 1) {
        ax += __shfl_down_sync(0xFFFFFFFFu, ax, o);
        ay += __shfl_down_sync(0xFFFFFFFFu, ay, o);
        az += __shfl_down_sync(0xFFFFFFFFu, az, o);
    }
    __shared__ float sx[4], sy[4], sz[4];
    if (lane == 0) { sx[wid] = ax; sy[wid] = ay; sz[wid] = az; }
    __syncthreads();
    if (wid == 0) {
        float rx = (lane < 4) ? sx[lane] : 0.f;
        float ry = (lane < 4) ? sy[lane] : 0.f;
        float rz = (lane < 4) ? sz[lane] : 0.f;
#pragma unroll
        for (int o = 2; o > 0; o >>= 1) {
            rx += __shfl_down_sync(0xFFFFFFFFu, rx, o);
            ry += __shfl_down_sync(0xFFFFFFFFu, ry, o);
            rz += __shfl_down_sync(0xFFFFFFFFu, rz, o);
        }
        const float scale = 0.3779644730092272f / (float)N;
        float g0 = __shfl_sync(0xFFFFFFFFu, rx, 0) * scale;
        float g1 = __shfl_sync(0xFFFFFFFFu, ry, 0) * scale;
        float g2 = __shfl_sync(0xFFFFFFFFu, rz, 0) * scale;
        float o0 = 0.f, o1 = 0.f, o2 = 0.f;
#pragma unroll
        for (int r = 0; r < HID / 32; r++) {
            int j = lane + r * 32;
            float h = fmaf(W1[j * 3 + 0], g0,
                      fmaf(W1[j * 3 + 1], g1,
                      fmaf(W1[j * 3 + 2], g2, b1[j])));
            h = fmaxf(h, 0.f);
            o0 = fmaf(W2[0 * HID + j], h, o0);
            o1 = fmaf(W2[1 * HID + j], h, o1);
            o2 = fmaf(W2[2 * HID + j], h, o2);
        }
#pragma unroll
        for (int o = 16; o > 0; o >>= 1) {
            o0 += __shfl_down_sync(0xFFFFFFFFu, o0, o);
            o1 += __shfl_down_sync(0xFFFFFFFFu, o1, o);
            o2 += __shfl_down_sync(0xFFFFFFFFu, o2, o);
        }
        if (lane == 0) {
            out[b * 3 + 0] = o0 + b2[0];
            out[b * 3 + 1] = o1 + b2[1];
            out[b * 3 + 2] = o2 + b2[2];
        }
    }
}

extern "C" void kernel_launch(void* const* d_in, const int* in_sizes, int n_in,
                              void* d_out, int out_size)
{
    const float* feats = (const float*)d_in[0];
    const float* coors = (const float*)d_in[1];
    // d_in[2] = adj_mat, intentionally unused
    const float* W_tp  = (const float*)d_in[3];
    const float* W1    = (const float*)d_in[4];
    const float* b1    = (const float*)d_in[5];
    const float* W2    = (const float*)d_in[6];
    const float* b2    = (const float*)d_in[7];
    float* out = (float*)d_out;

    const int B = out_size / 3;           // output [B,3]
    const int N = in_sizes[1] / (B * 3);  // coors [B,N,3]

    if (N == N_FIXED) {
        dipole_r12_kernel<<<B, THREADS>>>(feats, coors, W_tp, W1, b1, W2, b2, out);
    } else {
        dipole_ldg_kernel<<<B, THREADS>>>(feats, coors, W_tp, W1, b1, W2, b2, out, N);
    }
}

// round 13
// speedup vs baseline: 1.1341x; 1.0366x over previous
#include <cuda_runtime.h>
#include <cstdint>

// DipolePredictorE3NN — FINAL (R13): reconfirm best-measured variant (R4,
// 8.096us). 12 rounds establish a ~2.6TB/s per-SM outstanding-fill ceiling
// that binds all transports (LDG any width, TMA, hybrids) equally; 21MB
// single-pass read => ~8us floor. Structure: both tiles via cp.async.bulk,
// one mbarrier, compute from smem, short epilogue.
//   d_in[0] feats [B,N,7] f32 | d_in[1] coors [B,N,3] f32 | d_in[2] adj (UNUSED)
//   d_in[3] W_tp[7] | d_in[4] W1[128,3] | d_in[5] b1[128] | d_in[6] W2[3,128] | d_in[7] b2[3]
// Output: [B,3] f32

#define NS 7
#define HID 128
#define THREADS 128
#define N_FIXED 512
#define FEATS_BYTES (N_FIXED * NS * 4)   // 14336
#define COORS_BYTES (N_FIXED * 3 * 4)    // 6144

__device__ __forceinline__ uint32_t smem_u32(const void* p) {
    uint32_t a;
    asm("{ .reg .u64 t; cvta.to.shared.u64 t, %1; cvt.u32.u64 %0, t; }"
        : "=r"(a) : "l"(p));
    return a;
}

__device__ __forceinline__ void mbar_wait0(uint32_t mbar) {
    uint32_t done;
    asm volatile(
        "{ .reg .pred p; mbarrier.try_wait.parity.shared.b64 p, [%1], 0; "
        "selp.b32 %0, 1, 0, p; }"
        : "=r"(done) : "r"(mbar) : "memory");
    if (!done) {
        asm volatile(
            "{ .reg .pred P1;\n"
            "W_%=: mbarrier.try_wait.parity.shared.b64 P1, [%0], 0, 0x989680;\n"
            "@P1 bra.uni D_%=;\n"
            "bra.uni W_%=;\n"
            "D_%=: }"
            :: "r"(mbar) : "memory");
    }
}

// ---------- fast path: N==512 ----------
__global__ __launch_bounds__(THREADS)
void dipole_final_kernel(const float* __restrict__ feats,
                         const float* __restrict__ coors,
                         const float* __restrict__ W_tp,
                         const float* __restrict__ W1,
                         const float* __restrict__ b1,
                         const float* __restrict__ W2,
                         const float* __restrict__ b2,
                         float* __restrict__ out)
{
    __shared__ __align__(16) float s_feats[N_FIXED * NS];  // 14336 B
    __shared__ __align__(16) float s_coors[N_FIXED * 3];   // 6144 B
    __shared__ __align__(8)  uint64_t s_mbar;
    __shared__ float sx[4], sy[4], sz[4];

    const int b    = blockIdx.x;
    const int tid  = threadIdx.x;
    const int lane = tid & 31;
    const int wid  = tid >> 5;

    const uint32_t mbar = smem_u32(&s_mbar);

    if (tid == 0) {
        asm volatile("mbarrier.init.shared.b64 [%0], 1;" :: "r"(mbar) : "memory");
    }
    __syncthreads();

    if (tid == 0) {
        asm volatile("mbarrier.arrive.expect_tx.shared.b64 _, [%0], %1;"
                     :: "r"(mbar), "r"((uint32_t)(FEATS_BYTES + COORS_BYTES)) : "memory");
        const char* gf = (const char*)(feats + (size_t)b * N_FIXED * NS);
        const char* gc = (const char*)(coors + (size_t)b * N_FIXED * 3);
        asm volatile(
            "cp.async.bulk.shared::cta.global.mbarrier::complete_tx::bytes "
            "[%0], [%1], %2, [%3];"
            :: "r"(smem_u32(s_feats)), "l"(gf), "r"((uint32_t)FEATS_BYTES), "r"(mbar)
            : "memory");
        asm volatile(
            "cp.async.bulk.shared::cta.global.mbarrier::complete_tx::bytes "
            "[%0], [%1], %2, [%3];"
            :: "r"(smem_u32(s_coors)), "l"(gc), "r"((uint32_t)COORS_BYTES), "r"(mbar)
            : "memory");
    }

    // Broadcast TP weights while the copies are in flight.
    float w[NS];
#pragma unroll
    for (int i = 0; i < NS; i++) w[i] = __ldg(&W_tp[i]);

    mbar_wait0(mbar);

    // Thread tid owns 4 consecutive nodes; all reads from conflict-free smem.
    float ax = 0.f, ay = 0.f, az = 0.f;
    {
        const float4* f4 = reinterpret_cast<const float4*>(s_feats) + tid * 7;
        float4 ff4[7];
#pragma unroll
        for (int i = 0; i < 7; i++) ff4[i] = f4[i];
        const float4* c4 = reinterpret_cast<const float4*>(s_coors) + tid * 3;
        float4 cc4[3];
#pragma unroll
        for (int i = 0; i < 3; i++) cc4[i] = c4[i];

        const float* ff = reinterpret_cast<const float*>(ff4);
        const float* cc = reinterpret_cast<const float*>(cc4);
#pragma unroll
        for (int j = 0; j < 4; j++) {
            float s = 0.f;
#pragma unroll
            for (int i = 0; i < NS; i++) s = fmaf(ff[j * NS + i], w[i], s);
            ax = fmaf(s, cc[j * 3 + 0], ax);
            ay = fmaf(s, cc[j * 3 + 1], ay);
            az = fmaf(s, cc[j * 3 + 2], az);
        }
    }

#pragma unroll
    for (int o = 16; o > 0; o >>= 1) {
        ax += __shfl_down_sync(0xFFFFFFFFu, ax, o);
        ay += __shfl_down_sync(0xFFFFFFFFu, ay, o);
        az += __shfl_down_sync(0xFFFFFFFFu, az, o);
    }
    if (lane == 0) { sx[wid] = ax; sy[wid] = ay; sz[wid] = az; }
    __syncthreads();

    if (wid == 0) {
        float rx = (lane < 4) ? sx[lane] : 0.f;
        float ry = (lane < 4) ? sy[lane] : 0.f;
        float rz = (lane < 4) ? sz[lane] : 0.f;
#pragma unroll
        for (int o = 2; o > 0; o >>= 1) {
            rx += __shfl_down_sync(0xFFFFFFFFu, rx, o);
            ry += __shfl_down_sync(0xFFFFFFFFu, ry, o);
            rz += __shfl_down_sync(0xFFFFFFFFu, rz, o);
        }
        const float scale = 0.3779644730092272f / (float)N_FIXED;  // 1/sqrt(7)/N
        float g0 = __shfl_sync(0xFFFFFFFFu, rx, 0) * scale;
        float g1 = __shfl_sync(0xFFFFFFFFu, ry, 0) * scale;
        float g2 = __shfl_sync(0xFFFFFFFFu, rz, 0) * scale;

        // MLP: out = W2 @ relu(W1 @ g + b1) + b2 ; each lane owns 4 hidden units.
        float o0 = 0.f, o1 = 0.f, o2 = 0.f;
#pragma unroll
        for (int r = 0; r < HID / 32; r++) {
            int j = lane + r * 32;
            float h = fmaf(W1[j * 3 + 0], g0,
                      fmaf(W1[j * 3 + 1], g1,
                      fmaf(W1[j * 3 + 2], g2, b1[j])));
            h = fmaxf(h, 0.f);
            o0 = fmaf(W2[0 * HID + j], h, o0);
            o1 = fmaf(W2[1 * HID + j], h, o1);
            o2 = fmaf(W2[2 * HID + j], h, o2);
        }
#pragma unroll
        for (int o = 16; o > 0; o >>= 1) {
            o0 += __shfl_down_sync(0xFFFFFFFFu, o0, o);
            o1 += __shfl_down_sync(0xFFFFFFFFu, o1, o);
            o2 += __shfl_down_sync(0xFFFFFFFFu, o2, o);
        }
        if (lane == 0) {
            out[b * 3 + 0] = o0 + b2[0];
            out[b * 3 + 1] = o1 + b2[1];
            out[b * 3 + 2] = o2 + b2[2];
        }
    }
}

// ---------- generic fallback (any N) ----------
__global__ __launch_bounds__(THREADS)
void dipole_ldg_kernel(const float* __restrict__ feats,
                       const float* __restrict__ coors,
                       const float* __restrict__ W_tp,
                       const float* __restrict__ W1,
                       const float* __restrict__ b1,
                       const float* __restrict__ W2,
                       const float* __restrict__ b2,
                       float* __restrict__ out,
                       int N)
{
    const int b    = blockIdx.x;
    const int tid  = threadIdx.x;
    const int lane = tid & 31;
    const int wid  = tid >> 5;
    float w[NS];
#pragma unroll
    for (int i = 0; i < NS; i++) w[i] = __ldg(&W_tp[i]);
    const float* fb = feats + (size_t)b * N * NS;
    const float* cb = coors + (size_t)b * N * 3;
    float ax = 0.f, ay = 0.f, az = 0.f;
    for (int n = tid; n < N; n += THREADS) {
        const float* fr = fb + (size_t)n * NS;
        float s = 0.f;
#pragma unroll
        for (int i = 0; i < NS; i++) s = fmaf(fr[i], w[i], s);
        const float* cr = cb + (size_t)n * 3;
        ax = fmaf(s, cr[0], ax);
        ay = fmaf(s, cr[1], ay);
        az = fmaf(s, cr[2], az);
    }
#pragma unroll
    for (int o = 16; o > 0; o >>= 1) {
        ax += __shfl_down_sync(0xFFFFFFFFu, ax, o);
        ay += __shfl_down_sync(0xFFFFFFFFu, ay, o);
        az += __shfl_down_sync(0xFFFFFFFFu, az, o);
    }
    __shared__ float sx[4], sy[4], sz[4];
    if (lane == 0) { sx[wid] = ax; sy[wid] = ay; sz[wid] = az; }
    __syncthreads();
    if (wid == 0) {
        float rx = (lane < 4) ? sx[lane] : 0.f;
        float ry = (lane < 4) ? sy[lane] : 0.f;
        float rz = (lane < 4) ? sz[lane] : 0.f;
#pragma unroll
        for (int o = 2; o > 0; o >>= 1) {
            rx += __shfl_down_sync(0xFFFFFFFFu, rx, o);
            ry += __shfl_down_sync(0xFFFFFFFFu, ry, o);
            rz += __shfl_down_sync(0xFFFFFFFFu, rz, o);
        }
        const float scale = 0.3779644730092272f / (float)N;
        float g0 = __shfl_sync(0xFFFFFFFFu, rx, 0) * scale;
        float g1 = __shfl_sync(0xFFFFFFFFu, ry, 0) * scale;
        float g2 = __shfl_sync(0xFFFFFFFFu, rz, 0) * scale;
        float o0 = 0.f, o1 = 0.f, o2 = 0.f;
#pragma unroll
        for (int r = 0; r < HID / 32; r++) {
            int j = lane + r * 32;
            float h = fmaf(W1[j * 3 + 0], g0,
                      fmaf(W1[j * 3 + 1], g1,
                      fmaf(W1[j * 3 + 2], g2, b1[j])));
            h = fmaxf(h, 0.f);
            o0 = fmaf(W2[0 * HID + j], h, o0);
            o1 = fmaf(W2[1 * HID + j], h, o1);
            o2 = fmaf(W2[2 * HID + j], h, o2);
        }
#pragma unroll
        for (int o = 16; o > 0; o >>= 1) {
            o0 += __shfl_down_sync(0xFFFFFFFFu, o0, o);
            o1 += __shfl_down_sync(0xFFFFFFFFu, o1, o);
            o2 += __shfl_down_sync(0xFFFFFFFFu, o2, o);
        }
        if (lane == 0) {
            out[b * 3 + 0] = o0 + b2[0];
            out[b * 3 + 1] = o1 + b2[1];
            out[b * 3 + 2] = o2 + b2[2];
        }
    }
}

extern "C" void kernel_launch(void* const* d_in, const int* in_sizes, int n_in,
                              void* d_out, int out_size)
{
    const float* feats = (const float*)d_in[0];
    const float* coors = (const float*)d_in[1];
    // d_in[2] = adj_mat, intentionally unused
    const float* W_tp  = (const float*)d_in[3];
    const float* W1    = (const float*)d_in[4];
    const float* b1    = (const float*)d_in[5];
    const float* W2    = (const float*)d_in[6];
    const float* b2    = (const float*)d_in[7];
    float* out = (float*)d_out;

    const int B = out_size / 3;           // output [B,3]
    const int N = in_sizes[1] / (B * 3);  // coors [B,N,3]

    if (N == N_FIXED) {
        dipole_final_kernel<<<B, THREADS>>>(feats, coors, W_tp, W1, b1, W2, b2, out);
    } else {
        dipole_ldg_kernel<<<B, THREADS>>>(feats, coors, W_tp, W1, b1, W2, b2, out, N);
    }
}

// round 14
// speedup vs baseline: 1.1772x; 1.0380x over previous
#include <cuda_runtime.h>
#include <cstdint>

// DipolePredictorE3NN — FINAL (R14): confirm + micro-trim the best variant
// (R13: TMA full-tile, single mbarrier, smem compute -> 7.872us).
// 13 rounds established an environment-level ~2.6TB/s ceiling binding all
// transports; 21MB single-pass read => ~7.8us floor. This round only nudges
// occupancy (launch_bounds minctas=8) and keeps the proven byte path.
//   d_in[0] feats [B,N,7] f32 | d_in[1] coors [B,N,3] f32 | d_in[2] adj (UNUSED)
//   d_in[3] W_tp[7] | d_in[4] W1[128,3] | d_in[5] b1[128] | d_in[6] W2[3,128] | d_in[7] b2[3]
// Output: [B,3] f32

#define NS 7
#define HID 128
#define THREADS 128
#define N_FIXED 512
#define FEATS_BYTES (N_FIXED * NS * 4)   // 14336
#define COORS_BYTES (N_FIXED * 3 * 4)    // 6144

__device__ __forceinline__ uint32_t smem_u32(const void* p) {
    uint32_t a;
    asm("{ .reg .u64 t; cvta.to.shared.u64 t, %1; cvt.u32.u64 %0, t; }"
        : "=r"(a) : "l"(p));
    return a;
}

__device__ __forceinline__ void mbar_wait0(uint32_t mbar) {
    uint32_t done;
    asm volatile(
        "{ .reg .pred p; mbarrier.try_wait.parity.shared.b64 p, [%1], 0; "
        "selp.b32 %0, 1, 0, p; }"
        : "=r"(done) : "r"(mbar) : "memory");
    if (!done) {
        asm volatile(
            "{ .reg .pred P1;\n"
            "W_%=: mbarrier.try_wait.parity.shared.b64 P1, [%0], 0, 0x989680;\n"
            "@P1 bra.uni D_%=;\n"
            "bra.uni W_%=;\n"
            "D_%=: }"
            :: "r"(mbar) : "memory");
    }
}

// ---------- fast path: N==512 ----------
__global__ __launch_bounds__(THREADS, 8)
void dipole_final_kernel(const float* __restrict__ feats,
                         const float* __restrict__ coors,
                         const float* __restrict__ W_tp,
                         const float* __restrict__ W1,
                         const float* __restrict__ b1,
                         const float* __restrict__ W2,
                         const float* __restrict__ b2,
                         float* __restrict__ out)
{
    __shared__ __align__(16) float s_feats[N_FIXED * NS];  // 14336 B
    __shared__ __align__(16) float s_coors[N_FIXED * 3];   // 6144 B
    __shared__ __align__(8)  uint64_t s_mbar;
    __shared__ float sx[4], sy[4], sz[4];

    const int b    = blockIdx.x;
    const int tid  = threadIdx.x;
    const int lane = tid & 31;
    const int wid  = tid >> 5;

    const uint32_t mbar = smem_u32(&s_mbar);

    if (tid == 0) {
        asm volatile("mbarrier.init.shared.b64 [%0], 1;" :: "r"(mbar) : "memory");
    }
    __syncthreads();

    if (tid == 0) {
        asm volatile("mbarrier.arrive.expect_tx.shared.b64 _, [%0], %1;"
                     :: "r"(mbar), "r"((uint32_t)(FEATS_BYTES + COORS_BYTES)) : "memory");
        const char* gf = (const char*)(feats + (size_t)b * N_FIXED * NS);
        const char* gc = (const char*)(coors + (size_t)b * N_FIXED * 3);
        asm volatile(
            "cp.async.bulk.shared::cta.global.mbarrier::complete_tx::bytes "
            "[%0], [%1], %2, [%3];"
            :: "r"(smem_u32(s_feats)), "l"(gf), "r"((uint32_t)FEATS_BYTES), "r"(mbar)
            : "memory");
        asm volatile(
            "cp.async.bulk.shared::cta.global.mbarrier::complete_tx::bytes "
            "[%0], [%1], %2, [%3];"
            :: "r"(smem_u32(s_coors)), "l"(gc), "r"((uint32_t)COORS_BYTES), "r"(mbar)
            : "memory");
    }

    // Broadcast TP weights while the copies are in flight.
    float w[NS];
#pragma unroll
    for (int i = 0; i < NS; i++) w[i] = __ldg(&W_tp[i]);

    mbar_wait0(mbar);

    // Thread tid owns 4 consecutive nodes; all reads from conflict-free smem.
    float ax = 0.f, ay = 0.f, az = 0.f;
    {
        const float4* f4 = reinterpret_cast<const float4*>(s_feats) + tid * 7;
        float4 ff4[7];
#pragma unroll
        for (int i = 0; i < 7; i++) ff4[i] = f4[i];
        const float4* c4 = reinterpret_cast<const float4*>(s_coors) + tid * 3;
        float4 cc4[3];
#pragma unroll
        for (int i = 0; i < 3; i++) cc4[i] = c4[i];

        const float* ff = reinterpret_cast<const float*>(ff4);
        const float* cc = reinterpret_cast<const float*>(cc4);
#pragma unroll
        for (int j = 0; j < 4; j++) {
            float s = 0.f;
#pragma unroll
            for (int i = 0; i < NS; i++) s = fmaf(ff[j * NS + i], w[i], s);
            ax = fmaf(s, cc[j * 3 + 0], ax);
            ay = fmaf(s, cc[j * 3 + 1], ay);
            az = fmaf(s, cc[j * 3 + 2], az);
        }
    }

#pragma unroll
    for (int o = 16; o > 0; o >>= 1) {
        ax += __shfl_down_sync(0xFFFFFFFFu, ax, o);
        ay += __shfl_down_sync(0xFFFFFFFFu, ay, o);
        az += __shfl_down_sync(0xFFFFFFFFu, az, o);
    }
    if (lane == 0) { sx[wid] = ax; sy[wid] = ay; sz[wid] = az; }
    __syncthreads();

    if (wid == 0) {
        float rx = (lane < 4) ? sx[lane] : 0.f;
        float ry = (lane < 4) ? sy[lane] : 0.f;
        float rz = (lane < 4) ? sz[lane] : 0.f;
#pragma unroll
        for (int o = 2; o > 0; o >>= 1) {
            rx += __shfl_down_sync(0xFFFFFFFFu, rx, o);
            ry += __shfl_down_sync(0xFFFFFFFFu, ry, o);
            rz += __shfl_down_sync(0xFFFFFFFFu, rz, o);
        }
        const float scale = 0.3779644730092272f / (float)N_FIXED;  // 1/sqrt(7)/N
        float g0 = __shfl_sync(0xFFFFFFFFu, rx, 0) * scale;
        float g1 = __shfl_sync(0xFFFFFFFFu, ry, 0) * scale;
        float g2 = __shfl_sync(0xFFFFFFFFu, rz, 0) * scale;

        // MLP: out = W2 @ relu(W1 @ g + b1) + b2 ; each lane owns 4 hidden units.
        float o0 = 0.f, o1 = 0.f, o2 = 0.f;
#pragma unroll
        for (int r = 0; r < HID / 32; r++) {
            int j = lane + r * 32;
            float h = fmaf(W1[j * 3 + 0], g0,
                      fmaf(W1[j * 3 + 1], g1,
                      fmaf(W1[j * 3 + 2], g2, b1[j])));
            h = fmaxf(h, 0.f);
            o0 = fmaf(W2[0 * HID + j], h, o0);
            o1 = fmaf(W2[1 * HID + j], h, o1);
            o2 = fmaf(W2[2 * HID + j], h, o2);
        }
#pragma unroll
        for (int o = 16; o > 0; o >>= 1) {
            o0 += __shfl_down_sync(0xFFFFFFFFu, o0, o);
            o1 += __shfl_down_sync(0xFFFFFFFFu, o1, o);
            o2 += __shfl_down_sync(0xFFFFFFFFu, o2, o);
        }
        if (lane == 0) {
            out[b * 3 + 0] = o0 + b2[0];
            out[b * 3 + 1] = o1 + b2[1];
            out[b * 3 + 2] = o2 + b2[2];
        }
    }
}

// ---------- generic fallback (any N) ----------
__global__ __launch_bounds__(THREADS)
void dipole_ldg_kernel(const float* __restrict__ feats,
                       const float* __restrict__ coors,
                       const float* __restrict__ W_tp,
                       const float* __restrict__ W1,
                       const float* __restrict__ b1,
                       const float* __restrict__ W2,
                       const float* __restrict__ b2,
                       float* __restrict__ out,
                       int N)
{
    const int b    = blockIdx.x;
    const int tid  = threadIdx.x;
    const int lane = tid & 31;
    const int wid  = tid >> 5;
    float w[NS];
#pragma unroll
    for (int i = 0; i < NS; i++) w[i] = __ldg(&W_tp[i]);
    const float* fb = feats + (size_t)b * N * NS;
    const float* cb = coors + (size_t)b * N * 3;
    float ax = 0.f, ay = 0.f, az = 0.f;
    for (int n = tid; n < N; n += THREADS) {
        const float* fr = fb + (size_t)n * NS;
        float s = 0.f;
#pragma unroll
        for (int i = 0; i < NS; i++) s = fmaf(fr[i], w[i], s);
        const float* cr = cb + (size_t)n * 3;
        ax = fmaf(s, cr[0], ax);
        ay = fmaf(s, cr[1], ay);
        az = fmaf(s, cr[2], az);
    }
#pragma unroll
    for (int o = 16; o > 0; o >>= 1) {
        ax += __shfl_down_sync(0xFFFFFFFFu, ax, o);
        ay += __shfl_down_sync(0xFFFFFFFFu, ay, o);
        az += __shfl_down_sync(0xFFFFFFFFu, az, o);
    }
    __shared__ float sx[4], sy[4], sz[4];
    if (lane == 0) { sx[wid] = ax; sy[wid] = ay; sz[wid] = az; }
    __syncthreads();
    if (wid == 0) {
        float rx = (lane < 4) ? sx[lane] : 0.f;
        float ry = (lane < 4) ? sy[lane] : 0.f;
        float rz = (lane < 4) ? sz[lane] : 0.f;
#pragma unroll
        for (int o = 2; o > 0; o >>= 1) {
            rx += __shfl_down_sync(0xFFFFFFFFu, rx, o);
            ry += __shfl_down_sync(0xFFFFFFFFu, ry, o);
            rz += __shfl_down_sync(0xFFFFFFFFu, rz, o);
        }
        const float scale = 0.3779644730092272f / (float)N;
        float g0 = __shfl_sync(0xFFFFFFFFu, rx, 0) * scale;
        float g1 = __shfl_sync(0xFFFFFFFFu, ry, 0) * scale;
        float g2 = __shfl_sync(0xFFFFFFFFu, rz, 0) * scale;
        float o0 = 0.f, o1 = 0.f, o2 = 0.f;
#pragma unroll
        for (int r = 0; r < HID / 32; r++) {
            int j = lane + r * 32;
            float h = fmaf(W1[j * 3 + 0], g0,
                      fmaf(W1[j * 3 + 1], g1,
                      fmaf(W1[j * 3 + 2], g2, b1[j])));
            h = fmaxf(h, 0.f);
            o0 = fmaf(W2[0 * HID + j], h, o0);
            o1 = fmaf(W2[1 * HID + j], h, o1);
            o2 = fmaf(W2[2 * HID + j], h, o2);
        }
#pragma unroll
        for (int o = 16; o > 0; o >>= 1) {
            o0 += __shfl_down_sync(0xFFFFFFFFu, o0, o);
            o1 += __shfl_down_sync(0xFFFFFFFFu, o1, o);
            o2 += __shfl_down_sync(0xFFFFFFFFu, o2, o);
        }
        if (lane == 0) {
            out[b * 3 + 0] = o0 + b2[0];
            out[b * 3 + 1] = o1 + b2[1];
            out[b * 3 + 2] = o2 + b2[2];
        }
    }
}

extern "C" void kernel_launch(void* const* d_in, const int* in_sizes, int n_in,
                              void* d_out, int out_size)
{
    const float* feats = (const float*)d_in[0];
    const float* coors = (const float*)d_in[1];
    // d_in[2] = adj_mat, intentionally unused
    const float* W_tp  = (const float*)d_in[3];
    const float* W1    = (const float*)d_in[4];
    const float* b1    = (const float*)d_in[5];
    const float* W2    = (const float*)d_in[6];
    const float* b2    = (const float*)d_in[7];
    float* out = (float*)d_out;

    const int B = out_size / 3;           // output [B,3]
    const int N = in_sizes[1] / (B * 3);  // coors [B,N,3]

    if (N == N_FIXED) {
        dipole_final_kernel<<<B, THREADS>>>(feats, coors, W_tp, W1, b1, W2, b2, out);
    } else {
        dipole_ldg_kernel<<<B, THREADS>>>(feats, coors, W_tp, W1, b1, W2, b2, out, N);
    }
}